// round 15
// baseline (speedup 1.0000x reference)
#include <cuda_runtime.h>
#include <math.h>

#define KC 256          // clusters
#define DIM 64          // dims
#define TILE_P 128      // points per chunk (assign kernel)
#define XD_STRIDE 129   // u64 stride for splatted X (pad: conflict-light)
#define NTHREADS 256
#define NBLOCKS 152
#define NITER 9         // MAX_ITER - 1

#define NMAX 500224
#define SCHUNK 1024     // counting-sort chunk
#define NCHUNK_MAX 512

typedef unsigned long long u64;

// Persistent device scratch (no allocations allowed)
__device__ float g_cent[KC * DIM];
__device__ float g_c2[KC];
__device__ float g_sum[KC * DIM];
__device__ float g_cnt[KC];
__device__ int   g_assign[NMAX];
__device__ int   g_sorted[NMAX];
__device__ int   g_hist[NCHUNK_MAX * KC];
__device__ int   g_chunkbase[NCHUNK_MAX * KC];
__device__ int   g_total[KC];
__device__ int   g_cbase[KC];

__device__ __forceinline__ u64 pack2(float lo, float hi) {
    u64 r;
    asm("mov.b64 %0, {%1, %2};" : "=l"(r) : "f"(lo), "f"(hi));
    return r;
}
__device__ __forceinline__ void unpack2(u64 v, float& lo, float& hi) {
    asm("mov.b64 {%0, %1}, %2;" : "=f"(lo), "=f"(hi) : "l"(v));
}
__device__ __forceinline__ u64 fma2(u64 a, u64 b, u64 c) {
    u64 d;
    asm("fma.rn.f32x2 %0, %1, %2, %3;" : "=l"(d) : "l"(a), "l"(b), "l"(c));
    return d;
}
__device__ __forceinline__ u64 add2(u64 a, u64 b) {
    u64 d;
    asm("add.rn.f32x2 %0, %1, %2;" : "=l"(d) : "l"(a), "l"(b));
    return d;
}

// XLA:GPU row-reduction (CONFIRMED bitwise @R14): lane i strided pair
//   P_i = (v[i]*v[i]) + (v[i+32]*v[i+32])   (strict mul/add)
// then butterfly tree offsets 16,8,4,2,1.
__device__ __forceinline__ float sumsq64_warpstrided(const float* v, int stride) {
    float P[32];
    #pragma unroll
    for (int i = 0; i < 32; i++) {
        float a = v[i * stride];
        float b = v[(i + 32) * stride];
        P[i] = __fadd_rn(__fmul_rn(a, a), __fmul_rn(b, b));
    }
    #pragma unroll
    for (int off = 16; off > 0; off >>= 1)
        #pragma unroll
        for (int i = 0; i < 16; i++)
            if (i < off) P[i] = __fadd_rn(P[i], P[i + off]);
    return P[0];
}

// Same reduction reading the LO half of splatted u64 entries (values bitwise
// identical to the float-array version: splat stores (x,x)).
__device__ __forceinline__ float sumsq64_warpstrided_lo(const u64* v, int stride) {
    float P[32];
    #pragma unroll
    for (int i = 0; i < 32; i++) {
        float a = ((const float*)(v + (size_t)i * stride))[0];
        float b = ((const float*)(v + (size_t)(i + 32) * stride))[0];
        P[i] = __fadd_rn(__fmul_rn(a, a), __fmul_rn(b, b));
    }
    #pragma unroll
    for (int off = 16; off > 0; off >>= 1)
        #pragma unroll
        for (int i = 0; i < 16; i++)
            if (i < off) P[i] = __fadd_rn(P[i], P[i + off]);
    return P[0];
}

// Dummy kernels: align the harness's ncu capture window (6th launch) onto
// kmeans_assign_kernel for next-round profiling evidence.
__global__ void kmeans_dummy_kernel() {}

// ---------------------------------------------------------------------------
// Init: copy initial centroids; c2 via strided warp-tree reduce emulation.
// ---------------------------------------------------------------------------
__global__ void kmeans_init_kernel(const float* __restrict__ cinit) {
    int k = blockIdx.x;
    int t = threadIdx.x;
    __shared__ float sv[DIM];
    float v = cinit[k * DIM + t];
    g_cent[k * DIM + t] = v;
    sv[t] = v;
    __syncthreads();
    if (t == 0) g_c2[k] = sumsq64_warpstrided(sv, 1);
}

// ---------------------------------------------------------------------------
// Assignment: persistent blocks, register-tiled fp32 GEMM (fma.rn.f32x2,
// ascending-k single-accumulator chains — bitwise = reference GEMM).
// X is stored splatted (x,x) in u64 smem so xs2 operands load directly.
// d2 epilogue packed: add.rn.f32x2 + fma.rn.f32x2(-2,dot,s12), bitwise-equal
// to (x2+c2)-2*dot because 2*dot is exact in fp32.
// ---------------------------------------------------------------------------
__global__ __launch_bounds__(NTHREADS, 1)
void kmeans_assign_kernel(const float* __restrict__ data, int npoints,
                          float* __restrict__ assign_out) {
    extern __shared__ char smraw[];
    u64*   Xd   = (u64*)smraw;                       // [DIM][129] u64  66048 B
    float* Cs   = (float*)(Xd + DIM * XD_STRIDE);    // [DIM][KC]       65536 B
    float* c2s  = Cs + KC * DIM;                     // [KC]             1024 B
    float* sx2  = c2s + KC;                          // [TILE_P]          512 B
    float* smin = sx2 + TILE_P;                      // [TILE_P*16]      8192 B
    float* sm2  = smin + TILE_P * 16;                // [TILE_P]          512 B
    float* sm2r = sm2 + TILE_P;                      // [TILE_P]          512 B
    int*   sIdxMin = (int*)(sm2r + TILE_P);          // [TILE_P]          512 B

    const int tid = threadIdx.x;
    const int tx = tid & 15;       // cluster lane
    const int ty = tid >> 4;       // point group
    const int p0 = ty * 8;
    const int cb = 2 * tx;         // clusters: cb + 32*j + {0,1}
    const u64 NEG2 = pack2(-2.0f, -2.0f);

    for (int i = tid; i < KC * DIM; i += NTHREADS) {
        int d = i >> 8;
        int c = i & 255;
        Cs[i] = g_cent[c * DIM + d];
    }
    for (int i = tid; i < KC; i += NTHREADS) c2s[i] = g_c2[i];
    __syncthreads();

    const int nchunks = (npoints + TILE_P - 1) / TILE_P;
    for (int ch = blockIdx.x; ch < nchunks; ch += gridDim.x) {
        const int base = ch * TILE_P;
        const int np = min(TILE_P, npoints - base);

        // Load X chunk transposed & splatted: Xd[d][p] = (x, x)
        if (np == TILE_P) {
            const float4* src = (const float4*)(data + (size_t)base * DIM);
            for (int i = tid; i < TILE_P * DIM / 4; i += NTHREADS) {
                float4 v = src[i];
                int e = i * 4;
                int p = e >> 6;
                int d = e & 63;
                Xd[(d + 0) * XD_STRIDE + p] = pack2(v.x, v.x);
                Xd[(d + 1) * XD_STRIDE + p] = pack2(v.y, v.y);
                Xd[(d + 2) * XD_STRIDE + p] = pack2(v.z, v.z);
                Xd[(d + 3) * XD_STRIDE + p] = pack2(v.w, v.w);
            }
        } else {
            for (int i = tid; i < TILE_P * DIM; i += NTHREADS) {
                int p = i >> 6;
                int d = i & 63;
                float v = (p < np) ? data[(size_t)base * DIM + i] : 0.0f;
                Xd[d * XD_STRIDE + p] = pack2(v, v);
            }
        }
        __syncthreads();

        // x2: strided-pair warp-tree (lo halves — values identical)
        if (tid < TILE_P) sx2[tid] = sumsq64_warpstrided_lo(Xd + tid, XD_STRIDE);
        __syncthreads();

        // GEMM: acc = strict ascending-d FMA chain per output (f32x2 packed)
        u64 acc[8][8];
        #pragma unroll
        for (int i = 0; i < 8; i++)
            #pragma unroll
            for (int j = 0; j < 8; j++) acc[i][j] = 0ull;

        #pragma unroll 4
        for (int d = 0; d < DIM; d++) {
            u64 cs[8];
            const u64* cp = (const u64*)(Cs + d * KC + cb);
            #pragma unroll
            for (int j = 0; j < 8; j++) cs[j] = cp[16 * j];
            u64 xs2[8];
            const u64* xp = Xd + d * XD_STRIDE + p0;
            #pragma unroll
            for (int i = 0; i < 8; i++) xs2[i] = xp[i];
            #pragma unroll
            for (int i = 0; i < 8; i++)
                #pragma unroll
                for (int j = 0; j < 8; j++)
                    acc[i][j] = fma2(xs2[i], cs[j], acc[i][j]);
        }

        // Stage 1: per-thread local min of dd = max((x2+c2)-2*dot, 0)
        if (tid < TILE_P) sIdxMin[tid] = 0x7fffffff;
        #pragma unroll
        for (int i = 0; i < 8; i++) {
            float x2p = sx2[p0 + i];
            u64 x2pp = pack2(x2p, x2p);
            float mloc = 3.402823466e38f;
            #pragma unroll
            for (int j = 0; j < 8; j++) {
                int c = cb + 32 * j;
                u64 s12 = add2(x2pp, *(const u64*)(c2s + c));
                u64 dd2 = fma2(NEG2, acc[i][j], s12);
                float ddl, ddh;
                unpack2(dd2, ddl, ddh);
                ddl = fmaxf(ddl, 0.0f);
                ddh = fmaxf(ddh, 0.0f);
                mloc = fminf(mloc, fminf(ddl, ddh));
            }
            smin[(p0 + i) * 16 + tx] = mloc;
        }
        __syncthreads();

        // Stage 2: global min d2 per point + its IEEE sqrt
        if (tid < TILE_P) {
            float m = 3.402823466e38f;
            #pragma unroll
            for (int t = 0; t < 16; t++) m = fminf(m, smin[tid * 16 + t]);
            sm2[tid] = m;
            sm2r[tid] = __fsqrt_rn(m);
        }
        __syncthreads();

        // Stage 3: candidates within sqrt-collapse window; min index whose
        // IEEE sqrt equals sqrt(m2)  ==  argmin of dist with first-index ties.
        #pragma unroll
        for (int i = 0; i < 8; i++) {
            int p = p0 + i;
            float x2p = sx2[p];
            u64 x2pp = pack2(x2p, x2p);
            float m2 = sm2[p];
            float thr = __fadd_rn(m2, __fmul_rn(m2, 1e-6f));
            float sref = sm2r[p];
            #pragma unroll
            for (int j = 0; j < 8; j++) {
                int c = cb + 32 * j;
                u64 s12 = add2(x2pp, *(const u64*)(c2s + c));
                u64 dd2 = fma2(NEG2, acc[i][j], s12);
                float ddl, ddh;
                unpack2(dd2, ddl, ddh);
                ddl = fmaxf(ddl, 0.0f);
                ddh = fmaxf(ddh, 0.0f);
                if (ddl <= thr && __fsqrt_rn(ddl) == sref) atomicMin(&sIdxMin[p], c);
                if (ddh <= thr && __fsqrt_rn(ddh) == sref) atomicMin(&sIdxMin[p], c + 1);
            }
        }
        __syncthreads();

        if (tid < TILE_P && tid < np) {
            int bi = sIdxMin[tid];
            g_assign[base + tid] = bi;
            assign_out[base + tid] = (float)bi;
        }
        __syncthreads();
    }
}

// ---------------------------------------------------------------------------
// Stable counting sort of point indices by cluster (exact integer math).
// ---------------------------------------------------------------------------
__global__ void kmeans_hist_kernel(int npoints) {
    __shared__ int sh[KC];
    int ch = blockIdx.x;
    int t = threadIdx.x;
    sh[t] = 0;
    __syncthreads();
    int base = ch * SCHUNK;
    #pragma unroll
    for (int r = 0; r < SCHUNK / 256; r++) {
        int g = base + r * 256 + t;
        if (g < npoints) atomicAdd(&sh[g_assign[g]], 1);
    }
    __syncthreads();
    g_hist[ch * KC + t] = sh[t];
}

__global__ void kmeans_colscan_kernel(int nch) {
    __shared__ int s[NCHUNK_MAX];
    int k = blockIdx.x;
    int t = threadIdx.x;   // 512 threads
    int v = (t < nch) ? g_hist[t * KC + k] : 0;
    s[t] = v;
    __syncthreads();
    for (int off = 1; off < NCHUNK_MAX; off <<= 1) {
        int x = 0;
        if (t >= off) x = s[t - off];
        __syncthreads();
        if (t >= off) s[t] += x;
        __syncthreads();
    }
    if (t < nch) g_chunkbase[t * KC + k] = s[t] - v;  // exclusive
    if (t == NCHUNK_MAX - 1) g_total[k] = s[t];
}

__global__ void kmeans_basescan_kernel() {
    __shared__ int s[KC];
    int t = threadIdx.x;
    int v = g_total[t];
    s[t] = v;
    __syncthreads();
    for (int off = 1; off < KC; off <<= 1) {
        int x = 0;
        if (t >= off) x = s[t - off];
        __syncthreads();
        if (t >= off) s[t] += x;
        __syncthreads();
    }
    g_cbase[t] = s[t] - v;
}

__global__ void kmeans_scatter_kernel(int npoints) {
    __shared__ int sa[256];
    __shared__ int running[KC];
    int ch = blockIdx.x;
    int t = threadIdx.x;
    running[t] = 0;
    __syncthreads();
    int base = ch * SCHUNK;
    for (int r = 0; r < SCHUNK / 256; r++) {
        int g = base + r * 256 + t;
        int a = (g < npoints) ? g_assign[g] : (-1 - t);
        sa[t] = a;
        __syncthreads();
        int cnt_before = 0, cnt_total = 0;
        for (int j = 0; j < 256; j++) {
            int aj = sa[j];
            if (aj == a) {
                cnt_total++;
                if (j < t) cnt_before++;
            }
        }
        if (g < npoints) {
            int pos = g_cbase[a] + g_chunkbase[ch * KC + a] + running[a] + cnt_before;
            g_sorted[pos] = g;
        }
        __syncthreads();
        if (g < npoints && cnt_before == 0) running[a] += cnt_total;
        __syncthreads();
    }
}

// ---------------------------------------------------------------------------
// Ordered per-cluster sum: strict ascending point order, sequential __fadd_rn
// chain per (cluster, dim) — deterministic segment-sum.
// ---------------------------------------------------------------------------
__global__ __launch_bounds__(DIM)
void kmeans_clustersum_kernel(const float* __restrict__ data) {
    __shared__ int sIdx[64];
    int k = blockIdx.x;
    int t = threadIdx.x;   // dim
    int n = g_total[k];
    int base = g_cbase[k];
    float acc = 0.0f;
    for (int m0 = 0; m0 < n; m0 += 64) {
        int mm = min(64, n - m0);
        __syncthreads();
        if (t < mm) sIdx[t] = g_sorted[base + m0 + t];
        __syncthreads();
        int m = 0;
        for (; m + 8 <= mm; m += 8) {
            float v0 = data[(size_t)sIdx[m + 0] * DIM + t];
            float v1 = data[(size_t)sIdx[m + 1] * DIM + t];
            float v2 = data[(size_t)sIdx[m + 2] * DIM + t];
            float v3 = data[(size_t)sIdx[m + 3] * DIM + t];
            float v4 = data[(size_t)sIdx[m + 4] * DIM + t];
            float v5 = data[(size_t)sIdx[m + 5] * DIM + t];
            float v6 = data[(size_t)sIdx[m + 6] * DIM + t];
            float v7 = data[(size_t)sIdx[m + 7] * DIM + t];
            acc = __fadd_rn(acc, v0);
            acc = __fadd_rn(acc, v1);
            acc = __fadd_rn(acc, v2);
            acc = __fadd_rn(acc, v3);
            acc = __fadd_rn(acc, v4);
            acc = __fadd_rn(acc, v5);
            acc = __fadd_rn(acc, v6);
            acc = __fadd_rn(acc, v7);
        }
        for (; m < mm; m++)
            acc = __fadd_rn(acc, data[(size_t)sIdx[m] * DIM + t]);
    }
    g_sum[k * DIM + t] = acc;
    if (t == 0) g_cnt[k] = (float)n;
}

// ---------------------------------------------------------------------------
// Centroid update: mean (empty -> 0); c2 via strided warp-tree emulation.
// ---------------------------------------------------------------------------
__global__ void kmeans_update_kernel() {
    int k = blockIdx.x;
    int t = threadIdx.x;
    __shared__ float sv[DIM];
    float cnt = g_cnt[k];
    float s = g_sum[k * DIM + t];
    float v = (cnt > 0.0f) ? __fdiv_rn(s, fmaxf(cnt, 1.0f)) : 0.0f;
    g_cent[k * DIM + t] = v;
    sv[t] = v;
    __syncthreads();
    if (t == 0) g_c2[k] = sumsq64_warpstrided(sv, 1);
}

__global__ void kmeans_copyout_kernel(float* __restrict__ out) {
    int i = blockIdx.x * blockDim.x + threadIdx.x;
    if (i < KC * DIM) out[i] = g_cent[i];
}

// ---------------------------------------------------------------------------
extern "C" void kernel_launch(void* const* d_in, const int* in_sizes, int n_in,
                              void* d_out, int out_size) {
    const float* data;
    const float* cinit;
    int ndata;
    if (in_sizes[0] == KC * DIM && n_in > 1) {
        cinit = (const float*)d_in[0];
        data = (const float*)d_in[1];
        ndata = in_sizes[1];
    } else {
        data = (const float*)d_in[0];
        cinit = (const float*)d_in[1];
        ndata = in_sizes[0];
    }
    const int npoints = ndata / DIM;
    const int nch = (npoints + SCHUNK - 1) / SCHUNK;

    float* out = (float*)d_out;
    float* assign_out = out + KC * DIM;

    const size_t shbytes =
        (size_t)(DIM * XD_STRIDE) * sizeof(u64) +     // Xd splatted
        (size_t)(KC * DIM                              // Cs
                 + KC                                  // c2s
                 + TILE_P                              // sx2
                 + TILE_P * 16                         // smin
                 + TILE_P                              // sm2
                 + TILE_P                              // sm2r
                 + TILE_P)                             // sIdxMin
        * sizeof(float);

    cudaFuncSetAttribute(kmeans_assign_kernel,
                         cudaFuncAttributeMaxDynamicSharedMemorySize,
                         (int)shbytes);

    // Two dummies: put kmeans_assign_kernel in the ncu capture slot.
    kmeans_dummy_kernel<<<1, 32>>>();
    kmeans_dummy_kernel<<<1, 32>>>();
    kmeans_init_kernel<<<KC, DIM>>>(cinit);
    for (int it = 0; it < NITER; ++it) {
        kmeans_assign_kernel<<<NBLOCKS, NTHREADS, shbytes>>>(data, npoints, assign_out);
        kmeans_hist_kernel<<<nch, 256>>>(npoints);
        kmeans_colscan_kernel<<<KC, NCHUNK_MAX>>>(nch);
        kmeans_basescan_kernel<<<1, KC>>>();
        kmeans_scatter_kernel<<<nch, 256>>>(npoints);
        kmeans_clustersum_kernel<<<KC, DIM>>>(data);
        kmeans_update_kernel<<<KC, DIM>>>();
    }
    kmeans_copyout_kernel<<<(KC * DIM + 255) / 256, 256>>>(out);
}

// round 16
// speedup vs baseline: 1.1040x; 1.1040x over previous
#include <cuda_runtime.h>
#include <math.h>

#define KC 256          // clusters
#define DIM 64          // dims
#define TILE_P 128      // points per chunk (assign kernel)
#define XD_STRIDE 129   // u64 stride for splatted X
#define NTHREADS 512    // assign kernel threads (16 warps)
#define NBLOCKS 152
#define NITER 9         // MAX_ITER - 1

#define NMAX 500224
#define SCHUNK 1024     // counting-sort chunk
#define NCHUNK_MAX 512

typedef unsigned long long u64;

// Persistent device scratch (no allocations allowed)
__device__ float g_cent[KC * DIM];
__device__ float g_c2[KC];
__device__ float g_sum[KC * DIM];
__device__ float g_cnt[KC];
__device__ int   g_assign[NMAX];
__device__ int   g_sorted[NMAX];
__device__ int   g_hist[NCHUNK_MAX * KC];
__device__ int   g_chunkbase[NCHUNK_MAX * KC];
__device__ int   g_total[KC];
__device__ int   g_cbase[KC];

__device__ __forceinline__ u64 pack2(float lo, float hi) {
    u64 r;
    asm("mov.b64 %0, {%1, %2};" : "=l"(r) : "f"(lo), "f"(hi));
    return r;
}
__device__ __forceinline__ void unpack2(u64 v, float& lo, float& hi) {
    asm("mov.b64 {%0, %1}, %2;" : "=f"(lo), "=f"(hi) : "l"(v));
}
__device__ __forceinline__ u64 fma2(u64 a, u64 b, u64 c) {
    u64 d;
    asm("fma.rn.f32x2 %0, %1, %2, %3;" : "=l"(d) : "l"(a), "l"(b), "l"(c));
    return d;
}
__device__ __forceinline__ u64 add2(u64 a, u64 b) {
    u64 d;
    asm("add.rn.f32x2 %0, %1, %2;" : "=l"(d) : "l"(a), "l"(b));
    return d;
}

// XLA:GPU row-reduction (CONFIRMED bitwise @R14): lane i strided pair
//   P_i = (v[i]*v[i]) + (v[i+32]*v[i+32])   (strict mul/add)
// then butterfly tree offsets 16,8,4,2,1.
__device__ __forceinline__ float sumsq64_warpstrided(const float* v, int stride) {
    float P[32];
    #pragma unroll
    for (int i = 0; i < 32; i++) {
        float a = v[i * stride];
        float b = v[(i + 32) * stride];
        P[i] = __fadd_rn(__fmul_rn(a, a), __fmul_rn(b, b));
    }
    #pragma unroll
    for (int off = 16; off > 0; off >>= 1)
        #pragma unroll
        for (int i = 0; i < 16; i++)
            if (i < off) P[i] = __fadd_rn(P[i], P[i + off]);
    return P[0];
}

// Same reduction reading the LO half of splatted u64 entries.
__device__ __forceinline__ float sumsq64_warpstrided_lo(const u64* v, int stride) {
    float P[32];
    #pragma unroll
    for (int i = 0; i < 32; i++) {
        float a = ((const float*)(v + (size_t)i * stride))[0];
        float b = ((const float*)(v + (size_t)(i + 32) * stride))[0];
        P[i] = __fadd_rn(__fmul_rn(a, a), __fmul_rn(b, b));
    }
    #pragma unroll
    for (int off = 16; off > 0; off >>= 1)
        #pragma unroll
        for (int i = 0; i < 16; i++)
            if (i < off) P[i] = __fadd_rn(P[i], P[i + off]);
    return P[0];
}

// Dummies: keep kmeans_assign_kernel in the ncu capture slot.
__global__ void kmeans_dummy_kernel() {}

// ---------------------------------------------------------------------------
// Init: copy initial centroids; c2 via strided warp-tree reduce emulation.
// ---------------------------------------------------------------------------
__global__ void kmeans_init_kernel(const float* __restrict__ cinit) {
    int k = blockIdx.x;
    int t = threadIdx.x;
    __shared__ float sv[DIM];
    float v = cinit[k * DIM + t];
    g_cent[k * DIM + t] = v;
    sv[t] = v;
    __syncthreads();
    if (t == 0) g_c2[k] = sumsq64_warpstrided(sv, 1);
}

// ---------------------------------------------------------------------------
// Assignment: 512 threads (16 warps/SM), each thread 4 points x 16 clusters.
// fma.rn.f32x2 ascending-k chains (bitwise = reference GEMM).
// ---------------------------------------------------------------------------
__global__ __launch_bounds__(NTHREADS, 1)
void kmeans_assign_kernel(const float* __restrict__ data, int npoints,
                          float* __restrict__ assign_out) {
    extern __shared__ char smraw[];
    u64*   Xd   = (u64*)smraw;                       // [DIM][129] u64  66048 B
    float* Cs   = (float*)(Xd + DIM * XD_STRIDE);    // [DIM][KC]       65536 B
    float* c2s  = Cs + KC * DIM;                     // [KC]
    float* sx2  = c2s + KC;                          // [TILE_P]
    float* smin = sx2 + TILE_P;                      // [TILE_P*16]
    float* sm2  = smin + TILE_P * 16;                // [TILE_P]
    float* sm2r = sm2 + TILE_P;                      // [TILE_P]
    int*   sIdxMin = (int*)(sm2r + TILE_P);          // [TILE_P]

    const int tid = threadIdx.x;
    const int tx = tid & 15;       // cluster lane
    const int ty = tid >> 4;       // point group (0..31)
    const int p0 = ty * 4;
    const int cb = 2 * tx;         // clusters: cb + 32*j + {0,1}
    const u64 NEG2 = pack2(-2.0f, -2.0f);

    for (int i = tid; i < KC * DIM; i += NTHREADS) {
        int d = i >> 8;
        int c = i & 255;
        Cs[i] = g_cent[c * DIM + d];
    }
    for (int i = tid; i < KC; i += NTHREADS) c2s[i] = g_c2[i];
    __syncthreads();

    const int nchunks = (npoints + TILE_P - 1) / TILE_P;
    for (int ch = blockIdx.x; ch < nchunks; ch += gridDim.x) {
        const int base = ch * TILE_P;
        const int np = min(TILE_P, npoints - base);

        // Load X chunk transposed & splatted: Xd[d][p] = (x, x)
        if (np == TILE_P) {
            const float4* src = (const float4*)(data + (size_t)base * DIM);
            for (int i = tid; i < TILE_P * DIM / 4; i += NTHREADS) {
                float4 v = src[i];
                int e = i * 4;
                int p = e >> 6;
                int d = e & 63;
                Xd[(d + 0) * XD_STRIDE + p] = pack2(v.x, v.x);
                Xd[(d + 1) * XD_STRIDE + p] = pack2(v.y, v.y);
                Xd[(d + 2) * XD_STRIDE + p] = pack2(v.z, v.z);
                Xd[(d + 3) * XD_STRIDE + p] = pack2(v.w, v.w);
            }
        } else {
            for (int i = tid; i < TILE_P * DIM; i += NTHREADS) {
                int p = i >> 6;
                int d = i & 63;
                float v = (p < np) ? data[(size_t)base * DIM + i] : 0.0f;
                Xd[d * XD_STRIDE + p] = pack2(v, v);
            }
        }
        __syncthreads();

        // x2: strided-pair warp-tree (lo halves — values identical)
        if (tid < TILE_P) sx2[tid] = sumsq64_warpstrided_lo(Xd + tid, XD_STRIDE);
        __syncthreads();

        // GEMM: acc = strict ascending-d FMA chain per output (f32x2 packed)
        u64 acc[4][8];
        #pragma unroll
        for (int i = 0; i < 4; i++)
            #pragma unroll
            for (int j = 0; j < 8; j++) acc[i][j] = 0ull;

        #pragma unroll 4
        for (int d = 0; d < DIM; d++) {
            u64 cs[8];
            const u64* cp = (const u64*)(Cs + d * KC + cb);
            #pragma unroll
            for (int j = 0; j < 8; j++) cs[j] = cp[16 * j];
            u64 xs2[4];
            const u64* xp = Xd + d * XD_STRIDE + p0;
            #pragma unroll
            for (int i = 0; i < 4; i++) xs2[i] = xp[i];
            #pragma unroll
            for (int i = 0; i < 4; i++)
                #pragma unroll
                for (int j = 0; j < 8; j++)
                    acc[i][j] = fma2(xs2[i], cs[j], acc[i][j]);
        }

        // Stage 1: per-thread local min of dd = max((x2+c2)-2*dot, 0)
        if (tid < TILE_P) sIdxMin[tid] = 0x7fffffff;
        #pragma unroll
        for (int i = 0; i < 4; i++) {
            float x2p = sx2[p0 + i];
            u64 x2pp = pack2(x2p, x2p);
            float mloc = 3.402823466e38f;
            #pragma unroll
            for (int j = 0; j < 8; j++) {
                int c = cb + 32 * j;
                u64 s12 = add2(x2pp, *(const u64*)(c2s + c));
                u64 dd2 = fma2(NEG2, acc[i][j], s12);
                float ddl, ddh;
                unpack2(dd2, ddl, ddh);
                ddl = fmaxf(ddl, 0.0f);
                ddh = fmaxf(ddh, 0.0f);
                mloc = fminf(mloc, fminf(ddl, ddh));
            }
            smin[(p0 + i) * 16 + tx] = mloc;
        }
        __syncthreads();

        // Stage 2: global min d2 per point + its IEEE sqrt
        if (tid < TILE_P) {
            float m = 3.402823466e38f;
            #pragma unroll
            for (int t = 0; t < 16; t++) m = fminf(m, smin[tid * 16 + t]);
            sm2[tid] = m;
            sm2r[tid] = __fsqrt_rn(m);
        }
        __syncthreads();

        // Stage 3: candidates within sqrt-collapse window; min index whose
        // IEEE sqrt equals sqrt(m2)  ==  argmin of dist with first-index ties.
        #pragma unroll
        for (int i = 0; i < 4; i++) {
            int p = p0 + i;
            float x2p = sx2[p];
            u64 x2pp = pack2(x2p, x2p);
            float m2 = sm2[p];
            float thr = __fadd_rn(m2, __fmul_rn(m2, 1e-6f));
            float sref = sm2r[p];
            #pragma unroll
            for (int j = 0; j < 8; j++) {
                int c = cb + 32 * j;
                u64 s12 = add2(x2pp, *(const u64*)(c2s + c));
                u64 dd2 = fma2(NEG2, acc[i][j], s12);
                float ddl, ddh;
                unpack2(dd2, ddl, ddh);
                ddl = fmaxf(ddl, 0.0f);
                ddh = fmaxf(ddh, 0.0f);
                if (ddl <= thr && __fsqrt_rn(ddl) == sref) atomicMin(&sIdxMin[p], c);
                if (ddh <= thr && __fsqrt_rn(ddh) == sref) atomicMin(&sIdxMin[p], c + 1);
            }
        }
        __syncthreads();

        if (tid < TILE_P && tid < np) {
            int bi = sIdxMin[tid];
            g_assign[base + tid] = bi;
            assign_out[base + tid] = (float)bi;
        }
        __syncthreads();
    }
}

// ---------------------------------------------------------------------------
// Stable counting sort of point indices by cluster (exact integer math).
// ---------------------------------------------------------------------------
__global__ void kmeans_hist_kernel(int npoints) {
    __shared__ int sh[KC];
    int ch = blockIdx.x;
    int t = threadIdx.x;
    sh[t] = 0;
    __syncthreads();
    int base = ch * SCHUNK;
    #pragma unroll
    for (int r = 0; r < SCHUNK / 256; r++) {
        int g = base + r * 256 + t;
        if (g < npoints) atomicAdd(&sh[g_assign[g]], 1);
    }
    __syncthreads();
    g_hist[ch * KC + t] = sh[t];
}

__global__ void kmeans_colscan_kernel(int nch) {
    __shared__ int s[NCHUNK_MAX];
    int k = blockIdx.x;
    int t = threadIdx.x;   // 512 threads
    int v = (t < nch) ? g_hist[t * KC + k] : 0;
    s[t] = v;
    __syncthreads();
    for (int off = 1; off < NCHUNK_MAX; off <<= 1) {
        int x = 0;
        if (t >= off) x = s[t - off];
        __syncthreads();
        if (t >= off) s[t] += x;
        __syncthreads();
    }
    if (t < nch) g_chunkbase[t * KC + k] = s[t] - v;  // exclusive
    if (t == NCHUNK_MAX - 1) g_total[k] = s[t];
}

__global__ void kmeans_basescan_kernel() {
    __shared__ int s[KC];
    int t = threadIdx.x;
    int v = g_total[t];
    s[t] = v;
    __syncthreads();
    for (int off = 1; off < KC; off <<= 1) {
        int x = 0;
        if (t >= off) x = s[t - off];
        __syncthreads();
        if (t >= off) s[t] += x;
        __syncthreads();
    }
    g_cbase[t] = s[t] - v;
}

__global__ void kmeans_scatter_kernel(int npoints) {
    __shared__ int sa[256];
    __shared__ int running[KC];
    int ch = blockIdx.x;
    int t = threadIdx.x;
    running[t] = 0;
    __syncthreads();
    int base = ch * SCHUNK;
    for (int r = 0; r < SCHUNK / 256; r++) {
        int g = base + r * 256 + t;
        int a = (g < npoints) ? g_assign[g] : (-1 - t);
        sa[t] = a;
        __syncthreads();
        int cnt_before = 0, cnt_total = 0;
        for (int j = 0; j < 256; j++) {
            int aj = sa[j];
            if (aj == a) {
                cnt_total++;
                if (j < t) cnt_before++;
            }
        }
        if (g < npoints) {
            int pos = g_cbase[a] + g_chunkbase[ch * KC + a] + running[a] + cnt_before;
            g_sorted[pos] = g;
        }
        __syncthreads();
        if (g < npoints && cnt_before == 0) running[a] += cnt_total;
        __syncthreads();
    }
}

// ---------------------------------------------------------------------------
// Ordered per-cluster sum: strict ascending point order, sequential __fadd_rn
// chain per (cluster, dim). Batch-32 register pipeline: 32 row loads in
// flight + next-batch index prefetch; NO smem staging, NO per-batch syncs.
// Add order is unchanged (ascending, predicated) => bitwise identical.
// ---------------------------------------------------------------------------
__global__ __launch_bounds__(DIM)
void kmeans_clustersum_kernel(const float* __restrict__ data) {
    int k = blockIdx.x;
    int t = threadIdx.x;   // dim
    int n = g_total[k];
    int base = g_cbase[k];
    float acc = 0.0f;

    int cur[32];
    #pragma unroll
    for (int j = 0; j < 32; j++)
        cur[j] = (j < n) ? g_sorted[base + j] : 0;

    for (int m0 = 0; m0 < n; m0 += 32) {
        int mm = n - m0;             // valid count this batch (>=1)
        // Issue 32 independent row loads (predicated)
        float vals[32];
        #pragma unroll
        for (int j = 0; j < 32; j++)
            vals[j] = (j < mm) ? data[(size_t)cur[j] * DIM + t] : 0.0f;
        // Prefetch next batch's indices while loads are in flight
        int rem = n - (m0 + 32);
        int nxt[32];
        #pragma unroll
        for (int j = 0; j < 32; j++)
            nxt[j] = (j < rem) ? g_sorted[base + m0 + 32 + j] : 0;
        // Strict ascending adds
        #pragma unroll
        for (int j = 0; j < 32; j++)
            if (j < mm) acc = __fadd_rn(acc, vals[j]);
        #pragma unroll
        for (int j = 0; j < 32; j++) cur[j] = nxt[j];
    }
    g_sum[k * DIM + t] = acc;
    if (t == 0) g_cnt[k] = (float)n;
}

// ---------------------------------------------------------------------------
// Centroid update: mean (empty -> 0); c2 via strided warp-tree emulation.
// ---------------------------------------------------------------------------
__global__ void kmeans_update_kernel() {
    int k = blockIdx.x;
    int t = threadIdx.x;
    __shared__ float sv[DIM];
    float cnt = g_cnt[k];
    float s = g_sum[k * DIM + t];
    float v = (cnt > 0.0f) ? __fdiv_rn(s, fmaxf(cnt, 1.0f)) : 0.0f;
    g_cent[k * DIM + t] = v;
    sv[t] = v;
    __syncthreads();
    if (t == 0) g_c2[k] = sumsq64_warpstrided(sv, 1);
}

__global__ void kmeans_copyout_kernel(float* __restrict__ out) {
    int i = blockIdx.x * blockDim.x + threadIdx.x;
    if (i < KC * DIM) out[i] = g_cent[i];
}

// ---------------------------------------------------------------------------
extern "C" void kernel_launch(void* const* d_in, const int* in_sizes, int n_in,
                              void* d_out, int out_size) {
    const float* data;
    const float* cinit;
    int ndata;
    if (in_sizes[0] == KC * DIM && n_in > 1) {
        cinit = (const float*)d_in[0];
        data = (const float*)d_in[1];
        ndata = in_sizes[1];
    } else {
        data = (const float*)d_in[0];
        cinit = (const float*)d_in[1];
        ndata = in_sizes[0];
    }
    const int npoints = ndata / DIM;
    const int nch = (npoints + SCHUNK - 1) / SCHUNK;

    float* out = (float*)d_out;
    float* assign_out = out + KC * DIM;

    const size_t shbytes =
        (size_t)(DIM * XD_STRIDE) * sizeof(u64) +     // Xd splatted
        (size_t)(KC * DIM                              // Cs
                 + KC                                  // c2s
                 + TILE_P                              // sx2
                 + TILE_P * 16                         // smin
                 + TILE_P                              // sm2
                 + TILE_P                              // sm2r
                 + TILE_P)                             // sIdxMin
        * sizeof(float);

    cudaFuncSetAttribute(kmeans_assign_kernel,
                         cudaFuncAttributeMaxDynamicSharedMemorySize,
                         (int)shbytes);

    // Two dummies: keep kmeans_assign_kernel in the ncu capture slot.
    kmeans_dummy_kernel<<<1, 32>>>();
    kmeans_dummy_kernel<<<1, 32>>>();
    kmeans_init_kernel<<<KC, DIM>>>(cinit);
    for (int it = 0; it < NITER; ++it) {
        kmeans_assign_kernel<<<NBLOCKS, NTHREADS, shbytes>>>(data, npoints, assign_out);
        kmeans_hist_kernel<<<nch, 256>>>(npoints);
        kmeans_colscan_kernel<<<KC, NCHUNK_MAX>>>(nch);
        kmeans_basescan_kernel<<<1, KC>>>();
        kmeans_scatter_kernel<<<nch, 256>>>(npoints);
        kmeans_clustersum_kernel<<<KC, DIM>>>(data);
        kmeans_update_kernel<<<KC, DIM>>>();
    }
    kmeans_copyout_kernel<<<(KC * DIM + 255) / 256, 256>>>(out);
}